// round 1
// baseline (speedup 1.0000x reference)
#include <cuda_runtime.h>
#include <cuda_bf16.h>
#include <cstdint>

using bf16 = __nv_bfloat16;
using bf162 = __nv_bfloat162;

// Problem constants
constexpr int B_  = 4;
constexpr int S_  = 4096;
constexpr int DM_ = 2048;
constexpr int DH_ = 64;
constexpr int MT_ = B_ * S_;          // 16384 total rows
// softmax scale (d_tensor=32 per reference) folded with log2(e) into qh
constexpr float FOLD = 1.4426950408889634f * 0.17677669529663687f;

// ---------------------------------------------------------------------------
// Scratch (device globals — no allocation allowed).
// qh/kh: row-major [MT][64] hi/lo bf16 splits.
// vt:    transposed [B][64][S] hi/lo bf16 splits (d-major, keys contiguous)
//        so PV B-fragments load contiguous pairs along the key axis.
// ---------------------------------------------------------------------------
__device__ __align__(16) bf16 g_qh_hi[MT_ * DH_];
__device__ __align__(16) bf16 g_qh_lo[MT_ * DH_];
__device__ __align__(16) bf16 g_kh_hi[MT_ * DH_];
__device__ __align__(16) bf16 g_kh_lo[MT_ * DH_];
__device__ __align__(16) bf16 g_vt_hi[MT_ * DH_];
__device__ __align__(16) bf16 g_vt_lo[MT_ * DH_];

// ---------------------------------------------------------------------------
// mma.sync m16n8k16 bf16 (fp32 accumulate)
// A row-major fragment: a0=(g,2c|2c+1) a1=(g+8,..) a2=(g,8+2c..) a3=(g+8,8+2c..)
// B col fragment:       b0=(k=2c|2c+1, n=g) b1=(k=8+2c.., n=g)
// C: c0,c1=(g, 2c|2c+1)  c2,c3=(g+8, ...)
// ---------------------------------------------------------------------------
__device__ __forceinline__ void mma_bf16(float c[4], const uint32_t a[4], const uint32_t b[2]) {
    asm volatile(
        "mma.sync.aligned.m16n8k16.row.col.f32.bf16.bf16.f32 "
        "{%0,%1,%2,%3}, {%4,%5,%6,%7}, {%8,%9}, {%0,%1,%2,%3};\n"
        : "+f"(c[0]), "+f"(c[1]), "+f"(c[2]), "+f"(c[3])
        : "r"(a[0]), "r"(a[1]), "r"(a[2]), "r"(a[3]), "r"(b[0]), "r"(b[1]));
}

__device__ __forceinline__ float fast_exp2(float x) {
    float r;
    asm("ex2.approx.ftz.f32 %0, %1;" : "=f"(r) : "f"(x));
    return r;
}

// Split two floats into packed bf16 hi-pair and lo-pair (x in low half).
__device__ __forceinline__ void split2(float x, float y, uint32_t& hp, uint32_t& lp) {
    bf16 hx = __float2bfloat16(x);
    bf16 hy = __float2bfloat16(y);
    bf16 lx = __float2bfloat16(x - __bfloat162float(hx));
    bf16 ly = __float2bfloat16(y - __bfloat162float(hy));
    bf162 h = __halves2bfloat162(hx, hy);
    bf162 l = __halves2bfloat162(lx, ly);
    hp = *reinterpret_cast<uint32_t*>(&h);
    lp = *reinterpret_cast<uint32_t*>(&l);
}

// ---------------------------------------------------------------------------
// Projection kernel: out = X @ W^T + b with 3xBF16 compensation.
// blockIdx.y selects projection: 0: qh = k@Wq^T+bq (scaled by FOLD)
//                                1: kh = q@Wk^T+bk
//                                2: vh = v@Wv^T+bv (stored transposed)
// Block: 128 rows x 64 cols, 8 warps (16 rows each), K-tile = 32.
// ---------------------------------------------------------------------------
constexpr int PK   = 32;
constexpr int PSTR = PK + 8;   // 40-element row stride -> conflict-free frags

__global__ __launch_bounds__(256) void proj_kernel(
    const float* __restrict__ q, const float* __restrict__ k, const float* __restrict__ v,
    const float* __restrict__ Wq, const float* __restrict__ bq,
    const float* __restrict__ Wk, const float* __restrict__ bk,
    const float* __restrict__ Wv, const float* __restrict__ bv)
{
    __shared__ __align__(16) bf16 sXh[128 * PSTR];
    __shared__ __align__(16) bf16 sXl[128 * PSTR];
    __shared__ __align__(16) bf16 sWh[64 * PSTR];
    __shared__ __align__(16) bf16 sWl[64 * PSTR];

    const int p = blockIdx.y;
    // NOTE: reference swaps inputs (query proj applied to k, key proj to q).
    const float* X    = (p == 0) ? k  : (p == 1) ? q  : v;
    const float* W    = (p == 0) ? Wq : (p == 1) ? Wk : Wv;
    const float* bias = (p == 0) ? bq : (p == 1) ? bk : bv;

    const int row0 = blockIdx.x * 128;
    const int tid  = threadIdx.x;
    const int lane = tid & 31;
    const int w    = tid >> 5;
    const int g    = lane >> 2;
    const int c    = lane & 3;
    const int wr   = w * 16;

    float acc[8][4];
#pragma unroll
    for (int i = 0; i < 8; i++)
#pragma unroll
        for (int j = 0; j < 4; j++) acc[i][j] = 0.f;

    for (int kb = 0; kb < DM_; kb += PK) {
        __syncthreads();
        // Load X tile 128x32 fp32 -> hi/lo bf16 in smem
        for (int i = tid; i < 1024; i += 256) {
            int r  = i >> 3;
            int cq = (i & 7) * 4;
            float4 xv = *reinterpret_cast<const float4*>(&X[(size_t)(row0 + r) * DM_ + kb + cq]);
            float vals[4] = {xv.x, xv.y, xv.z, xv.w};
#pragma unroll
            for (int j = 0; j < 4; j++) {
                bf16 h = __float2bfloat16(vals[j]);
                sXh[r * PSTR + cq + j] = h;
                sXl[r * PSTR + cq + j] = __float2bfloat16(vals[j] - __bfloat162float(h));
            }
        }
        // Load W tile 64x32 fp32 -> hi/lo bf16 in smem
        for (int i = tid; i < 512; i += 256) {
            int r  = i >> 3;
            int cq = (i & 7) * 4;
            float4 wv = *reinterpret_cast<const float4*>(&W[(size_t)r * DM_ + kb + cq]);
            float vals[4] = {wv.x, wv.y, wv.z, wv.w};
#pragma unroll
            for (int j = 0; j < 4; j++) {
                bf16 h = __float2bfloat16(vals[j]);
                sWh[r * PSTR + cq + j] = h;
                sWl[r * PSTR + cq + j] = __float2bfloat16(vals[j] - __bfloat162float(h));
            }
        }
        __syncthreads();

#pragma unroll
        for (int kk = 0; kk < PK; kk += 16) {
            const int abase = (wr + g) * PSTR + kk + 2 * c;
            uint32_t ah[4], al[4];
            ah[0] = *reinterpret_cast<const uint32_t*>(&sXh[abase]);
            ah[1] = *reinterpret_cast<const uint32_t*>(&sXh[abase + 8 * PSTR]);
            ah[2] = *reinterpret_cast<const uint32_t*>(&sXh[abase + 8]);
            ah[3] = *reinterpret_cast<const uint32_t*>(&sXh[abase + 8 * PSTR + 8]);
            al[0] = *reinterpret_cast<const uint32_t*>(&sXl[abase]);
            al[1] = *reinterpret_cast<const uint32_t*>(&sXl[abase + 8 * PSTR]);
            al[2] = *reinterpret_cast<const uint32_t*>(&sXl[abase + 8]);
            al[3] = *reinterpret_cast<const uint32_t*>(&sXl[abase + 8 * PSTR + 8]);
#pragma unroll
            for (int nb = 0; nb < 8; nb++) {
                const int bbase = (nb * 8 + g) * PSTR + kk + 2 * c;
                uint32_t bh[2], bl[2];
                bh[0] = *reinterpret_cast<const uint32_t*>(&sWh[bbase]);
                bh[1] = *reinterpret_cast<const uint32_t*>(&sWh[bbase + 8]);
                bl[0] = *reinterpret_cast<const uint32_t*>(&sWl[bbase]);
                bl[1] = *reinterpret_cast<const uint32_t*>(&sWl[bbase + 8]);
                mma_bf16(acc[nb], ah, bh);   // hi*hi
                mma_bf16(acc[nb], ah, bl);   // hi*lo
                mma_bf16(acc[nb], al, bh);   // lo*hi
            }
        }
    }

    // Epilogue: add bias, fold scale (proj 0), split to hi/lo, store.
    const float fold = (p == 0) ? FOLD : 1.0f;
    bf16* outH = (p == 0) ? g_qh_hi : (p == 1) ? g_kh_hi : g_vt_hi;
    bf16* outL = (p == 0) ? g_qh_lo : (p == 1) ? g_kh_lo : g_vt_lo;

#pragma unroll
    for (int nb = 0; nb < 8; nb++) {
        const int col = nb * 8 + 2 * c;
        const float b0f = bias[col];
        const float b1f = bias[col + 1];
        const int r0 = row0 + wr + g;
        float v00 = (acc[nb][0] + b0f) * fold;
        float v01 = (acc[nb][1] + b1f) * fold;
        float v10 = (acc[nb][2] + b0f) * fold;
        float v11 = (acc[nb][3] + b1f) * fold;
        if (p < 2) {
            uint32_t hp, lp;
            split2(v00, v01, hp, lp);
            *reinterpret_cast<uint32_t*>(&outH[(size_t)r0 * 64 + col]) = hp;
            *reinterpret_cast<uint32_t*>(&outL[(size_t)r0 * 64 + col]) = lp;
            split2(v10, v11, hp, lp);
            *reinterpret_cast<uint32_t*>(&outH[(size_t)(r0 + 8) * 64 + col]) = hp;
            *reinterpret_cast<uint32_t*>(&outL[(size_t)(r0 + 8) * 64 + col]) = lp;
        } else {
            // transposed store: [b][d][s]
            const int bidx = r0 >> 12;
            const int s0   = r0 & 4095;
            const size_t base = (size_t)bidx * 64;
            float vals[4]   = {v00, v01, v10, v11};
            int   dcol[4]   = {col, col + 1, col, col + 1};
            int   srow[4]   = {s0, s0, s0 + 8, s0 + 8};
#pragma unroll
            for (int j = 0; j < 4; j++) {
                bf16 h = __float2bfloat16(vals[j]);
                outH[(base + dcol[j]) * S_ + srow[j]] = h;
                outL[(base + dcol[j]) * S_ + srow[j]] =
                    __float2bfloat16(vals[j] - __bfloat162float(h));
            }
        }
    }
}

// ---------------------------------------------------------------------------
// Flash-attention kernel. grid = (S/64, B). 128 threads = 4 warps x 16 rows.
// Q fragments register-resident (hi/lo). kh/vt tiles (BN=64) in smem,
// row stride 72 elements -> bank-conflict-free fragment loads.
// Softmax in exp2 domain (scale*log2e already folded into qh).
// ---------------------------------------------------------------------------
constexpr int ASTR = 72;

__global__ __launch_bounds__(128) void attn_kernel(float* __restrict__ out)
{
    __shared__ __align__(16) bf16 sKh[64 * ASTR];
    __shared__ __align__(16) bf16 sKl[64 * ASTR];
    __shared__ __align__(16) bf16 sVh[64 * ASTR];
    __shared__ __align__(16) bf16 sVl[64 * ASTR];

    const int qx   = blockIdx.x;
    const int b    = blockIdx.y;
    const int tid  = threadIdx.x;
    const int lane = tid & 31;
    const int w    = tid >> 5;
    const int g    = lane >> 2;
    const int c    = lane & 3;
    const int wr   = w * 16;
    const int row0 = b * S_ + qx * 64;

    // Load Q fragments (hi/lo) for the 4 k-steps of d=64, straight from global.
    uint32_t qh[4][4], ql[4][4];
    {
        const bf16* baseH = g_qh_hi + (size_t)row0 * 64;
        const bf16* baseL = g_qh_lo + (size_t)row0 * 64;
        const int r = wr + g;
#pragma unroll
        for (int kk4 = 0; kk4 < 4; kk4++) {
            const int col = kk4 * 16 + 2 * c;
            qh[kk4][0] = *reinterpret_cast<const uint32_t*>(&baseH[(size_t)r * 64 + col]);
            qh[kk4][1] = *reinterpret_cast<const uint32_t*>(&baseH[(size_t)(r + 8) * 64 + col]);
            qh[kk4][2] = *reinterpret_cast<const uint32_t*>(&baseH[(size_t)r * 64 + col + 8]);
            qh[kk4][3] = *reinterpret_cast<const uint32_t*>(&baseH[(size_t)(r + 8) * 64 + col + 8]);
            ql[kk4][0] = *reinterpret_cast<const uint32_t*>(&baseL[(size_t)r * 64 + col]);
            ql[kk4][1] = *reinterpret_cast<const uint32_t*>(&baseL[(size_t)(r + 8) * 64 + col]);
            ql[kk4][2] = *reinterpret_cast<const uint32_t*>(&baseL[(size_t)r * 64 + col + 8]);
            ql[kk4][3] = *reinterpret_cast<const uint32_t*>(&baseL[(size_t)(r + 8) * 64 + col + 8]);
        }
    }

    float o[8][4];
#pragma unroll
    for (int i = 0; i < 8; i++)
#pragma unroll
        for (int j = 0; j < 4; j++) o[i][j] = 0.f;
    float m0 = -1e30f, m1 = -1e30f, l0 = 0.f, l1 = 0.f;

    const uint32_t* ksrcH = reinterpret_cast<const uint32_t*>(g_kh_hi + (size_t)(b * S_) * 64);
    const uint32_t* ksrcL = reinterpret_cast<const uint32_t*>(g_kh_lo + (size_t)(b * S_) * 64);
    const uint32_t* vsrcH = reinterpret_cast<const uint32_t*>(g_vt_hi + (size_t)b * 64 * S_);
    const uint32_t* vsrcL = reinterpret_cast<const uint32_t*>(g_vt_lo + (size_t)b * 64 * S_);

    for (int jt = 0; jt < S_ / 64; jt++) {
        __syncthreads();
        // kh tile: 64 keys x 64 d (d contiguous)
        for (int i = tid; i < 2048; i += 128) {
            const int r  = i >> 5;
            const int cw = i & 31;
            reinterpret_cast<uint32_t*>(&sKh[r * ASTR])[cw] = ksrcH[(size_t)(jt * 64 + r) * 32 + cw];
            reinterpret_cast<uint32_t*>(&sKl[r * ASTR])[cw] = ksrcL[(size_t)(jt * 64 + r) * 32 + cw];
        }
        // vt tile: 64 d x 64 keys (keys contiguous — already transposed in global)
        for (int i = tid; i < 2048; i += 128) {
            const int d  = i >> 5;
            const int tw = i & 31;
            reinterpret_cast<uint32_t*>(&sVh[d * ASTR])[tw] = vsrcH[(size_t)d * (S_ / 2) + jt * 32 + tw];
            reinterpret_cast<uint32_t*>(&sVl[d * ASTR])[tw] = vsrcL[(size_t)d * (S_ / 2) + jt * 32 + tw];
        }
        __syncthreads();

        // S = Q K^T (3xBF16)
        float s[8][4];
#pragma unroll
        for (int i = 0; i < 8; i++)
#pragma unroll
            for (int j = 0; j < 4; j++) s[i][j] = 0.f;
#pragma unroll
        for (int kk4 = 0; kk4 < 4; kk4++) {
#pragma unroll
            for (int nb = 0; nb < 8; nb++) {
                const int bbase = (nb * 8 + g) * ASTR + kk4 * 16 + 2 * c;
                uint32_t bh[2], bl[2];
                bh[0] = *reinterpret_cast<const uint32_t*>(&sKh[bbase]);
                bh[1] = *reinterpret_cast<const uint32_t*>(&sKh[bbase + 8]);
                bl[0] = *reinterpret_cast<const uint32_t*>(&sKl[bbase]);
                bl[1] = *reinterpret_cast<const uint32_t*>(&sKl[bbase + 8]);
                mma_bf16(s[nb], qh[kk4], bh);
                mma_bf16(s[nb], qh[kk4], bl);
                mma_bf16(s[nb], ql[kk4], bh);
            }
        }

        // Online softmax (exp2 domain)
        float tm0 = -1e30f, tm1 = -1e30f;
#pragma unroll
        for (int nb = 0; nb < 8; nb++) {
            tm0 = fmaxf(tm0, fmaxf(s[nb][0], s[nb][1]));
            tm1 = fmaxf(tm1, fmaxf(s[nb][2], s[nb][3]));
        }
        tm0 = fmaxf(tm0, __shfl_xor_sync(0xffffffffu, tm0, 1));
        tm0 = fmaxf(tm0, __shfl_xor_sync(0xffffffffu, tm0, 2));
        tm1 = fmaxf(tm1, __shfl_xor_sync(0xffffffffu, tm1, 1));
        tm1 = fmaxf(tm1, __shfl_xor_sync(0xffffffffu, tm1, 2));
        const float nm0 = fmaxf(m0, tm0);
        const float nm1 = fmaxf(m1, tm1);
        const float al0 = fast_exp2(m0 - nm0);
        const float al1 = fast_exp2(m1 - nm1);
        m0 = nm0; m1 = nm1;
        float rs0 = 0.f, rs1 = 0.f;
#pragma unroll
        for (int nb = 0; nb < 8; nb++) {
            s[nb][0] = fast_exp2(s[nb][0] - m0); rs0 += s[nb][0];
            s[nb][1] = fast_exp2(s[nb][1] - m0); rs0 += s[nb][1];
            s[nb][2] = fast_exp2(s[nb][2] - m1); rs1 += s[nb][2];
            s[nb][3] = fast_exp2(s[nb][3] - m1); rs1 += s[nb][3];
        }
        rs0 += __shfl_xor_sync(0xffffffffu, rs0, 1);
        rs0 += __shfl_xor_sync(0xffffffffu, rs0, 2);
        rs1 += __shfl_xor_sync(0xffffffffu, rs1, 1);
        rs1 += __shfl_xor_sync(0xffffffffu, rs1, 2);
        l0 = l0 * al0 + rs0;
        l1 = l1 * al1 + rs1;
#pragma unroll
        for (int nb = 0; nb < 8; nb++) {
            o[nb][0] *= al0; o[nb][1] *= al0;
            o[nb][2] *= al1; o[nb][3] *= al1;
        }

        // O += P V (3xBF16): S C-frags re-pack directly into A-frags.
#pragma unroll
        for (int ku = 0; ku < 4; ku++) {
            uint32_t ph[4], pl[4];
            split2(s[2 * ku][0],     s[2 * ku][1],     ph[0], pl[0]);
            split2(s[2 * ku][2],     s[2 * ku][3],     ph[1], pl[1]);
            split2(s[2 * ku + 1][0], s[2 * ku + 1][1], ph[2], pl[2]);
            split2(s[2 * ku + 1][2], s[2 * ku + 1][3], ph[3], pl[3]);
#pragma unroll
            for (int nbd = 0; nbd < 8; nbd++) {
                const int vbase = (nbd * 8 + g) * ASTR + ku * 16 + 2 * c;
                uint32_t vh2[2], vl2[2];
                vh2[0] = *reinterpret_cast<const uint32_t*>(&sVh[vbase]);
                vh2[1] = *reinterpret_cast<const uint32_t*>(&sVh[vbase + 8]);
                vl2[0] = *reinterpret_cast<const uint32_t*>(&sVl[vbase]);
                vl2[1] = *reinterpret_cast<const uint32_t*>(&sVl[vbase + 8]);
                mma_bf16(o[nbd], ph, vh2);
                mma_bf16(o[nbd], ph, vl2);
                mma_bf16(o[nbd], pl, vh2);
            }
        }
    }

    // Normalize and write output (fp32)
    const float il0 = 1.f / l0;
    const float il1 = 1.f / l1;
#pragma unroll
    for (int nbd = 0; nbd < 8; nbd++) {
        const int colD = nbd * 8 + 2 * c;
        const size_t r = (size_t)(row0 + wr + g);
        float2 v0 = make_float2(o[nbd][0] * il0, o[nbd][1] * il0);
        float2 v1 = make_float2(o[nbd][2] * il1, o[nbd][3] * il1);
        *reinterpret_cast<float2*>(&out[r * 64 + colD])       = v0;
        *reinterpret_cast<float2*>(&out[(r + 8) * 64 + colD]) = v1;
    }
}

// ---------------------------------------------------------------------------
// kernel_launch: two graph-capturable launches, no allocation, no sync.
// Input order per metadata: q, k, v, Wq, bq, Wk, bk, Wv, bv
// ---------------------------------------------------------------------------
extern "C" void kernel_launch(void* const* d_in, const int* in_sizes, int n_in,
                              void* d_out, int out_size) {
    (void)in_sizes; (void)n_in; (void)out_size;
    const float* q  = (const float*)d_in[0];
    const float* k  = (const float*)d_in[1];
    const float* v  = (const float*)d_in[2];
    const float* Wq = (const float*)d_in[3];
    const float* bq = (const float*)d_in[4];
    const float* Wk = (const float*)d_in[5];
    const float* bk = (const float*)d_in[6];
    const float* Wv = (const float*)d_in[7];
    const float* bv = (const float*)d_in[8];
    float* out = (float*)d_out;

    proj_kernel<<<dim3(MT_ / 128, 3), 256>>>(q, k, v, Wq, bq, Wk, bk, Wv, bv);
    attn_kernel<<<dim3(S_ / 64, B_), 128>>>(out);
}

// round 3
// speedup vs baseline: 1.9823x; 1.9823x over previous
#include <cuda_runtime.h>
#include <cuda_bf16.h>
#include <cstdint>

using bf16 = __nv_bfloat16;
using bf162 = __nv_bfloat162;

// Problem constants
constexpr int B_  = 4;
constexpr int S_  = 4096;
constexpr int DM_ = 2048;
constexpr int DH_ = 64;
constexpr int MT_ = B_ * S_;          // 16384 total rows
constexpr int SPLIT = 4;              // key-dimension split for attention
// softmax scale (d_tensor=32 per reference) folded with log2(e) into qh
constexpr float FOLD = 1.4426950408889634f * 0.17677669529663687f;

// ---------------------------------------------------------------------------
// Scratch (device globals — no allocation allowed).
// ---------------------------------------------------------------------------
__device__ __align__(16) bf16 g_qh_hi[MT_ * DH_];
__device__ __align__(16) bf16 g_qh_lo[MT_ * DH_];
__device__ __align__(16) bf16 g_kh_hi[MT_ * DH_];
__device__ __align__(16) bf16 g_kh_lo[MT_ * DH_];
__device__ __align__(16) bf16 g_vt_hi[MT_ * DH_];   // [B][64][S] transposed
__device__ __align__(16) bf16 g_vt_lo[MT_ * DH_];
__device__ __align__(16) bf16 g_wh[3 * DH_ * DM_];  // pre-split weights hi
__device__ __align__(16) bf16 g_wl[3 * DH_ * DM_];  // pre-split weights lo
// split-attention partials
__device__ __align__(16) float g_po[SPLIT * MT_ * DH_];
__device__ float g_pm[SPLIT * MT_];
__device__ float g_pl[SPLIT * MT_];

// ---------------------------------------------------------------------------
// Helpers
// ---------------------------------------------------------------------------
__device__ __forceinline__ void mma_bf16(float c[4], const uint32_t a[4], const uint32_t b[2]) {
    asm volatile(
        "mma.sync.aligned.m16n8k16.row.col.f32.bf16.bf16.f32 "
        "{%0,%1,%2,%3}, {%4,%5,%6,%7}, {%8,%9}, {%0,%1,%2,%3};\n"
        : "+f"(c[0]), "+f"(c[1]), "+f"(c[2]), "+f"(c[3])
        : "r"(a[0]), "r"(a[1]), "r"(a[2]), "r"(a[3]), "r"(b[0]), "r"(b[1]));
}

__device__ __forceinline__ float fast_exp2(float x) {
    float r;
    asm("ex2.approx.ftz.f32 %0, %1;" : "=f"(r) : "f"(x));
    return r;
}

__device__ __forceinline__ void split2(float x, float y, uint32_t& hp, uint32_t& lp) {
    bf16 hx = __float2bfloat16(x);
    bf16 hy = __float2bfloat16(y);
    bf16 lx = __float2bfloat16(x - __bfloat162float(hx));
    bf16 ly = __float2bfloat16(y - __bfloat162float(hy));
    bf162 h = __halves2bfloat162(hx, hy);
    bf162 l = __halves2bfloat162(lx, ly);
    hp = *reinterpret_cast<uint32_t*>(&h);
    lp = *reinterpret_cast<uint32_t*>(&l);
}

__device__ __forceinline__ uint32_t sm_u32(const void* p) {
    return (uint32_t)__cvta_generic_to_shared(p);
}
__device__ __forceinline__ void cp16(uint32_t dst, const void* src) {
    asm volatile("cp.async.cg.shared.global [%0], [%1], 16;\n" :: "r"(dst), "l"(src));
}
#define CP_COMMIT() asm volatile("cp.async.commit_group;\n")
template<int N>
__device__ __forceinline__ void cp_wait() {
    asm volatile("cp.async.wait_group %0;\n" :: "n"(N));
}

// ---------------------------------------------------------------------------
// Weight pre-split: W (3 x 64 x 2048 fp32) -> hi/lo bf16
// ---------------------------------------------------------------------------
__global__ void wsplit_kernel(const float* __restrict__ Wq,
                              const float* __restrict__ Wk,
                              const float* __restrict__ Wv) {
    int i = blockIdx.x * 256 + threadIdx.x;
    if (i >= 3 * DH_ * DM_) return;
    int p = i / (DH_ * DM_);
    int j = i - p * (DH_ * DM_);
    const float* W = (p == 0) ? Wq : (p == 1) ? Wk : Wv;
    float v = W[j];
    bf16 h = __float2bfloat16(v);
    g_wh[i] = h;
    g_wl[i] = __float2bfloat16(v - __bfloat162float(h));
}

// ---------------------------------------------------------------------------
// Projection kernel (double-buffered cp.async).
// Block: 128 rows x 64 cols, 8 warps, K-tile = 32.
// smem per stage: X fp32 128x36 (18432B) + Wh/Wl bf16 64x40 (5120B each)
// ---------------------------------------------------------------------------
constexpr int PK    = 32;
constexpr int PXSTR = 36;             // fp32 elements
constexpr int PWSTR = 40;             // bf16 elements
constexpr int PSTAGE_BYTES = 128 * PXSTR * 4 + 2 * 64 * PWSTR * 2;  // 28672

__global__ __launch_bounds__(256) void proj_kernel(
    const float* __restrict__ q, const float* __restrict__ k, const float* __restrict__ v,
    const float* __restrict__ bq, const float* __restrict__ bk, const float* __restrict__ bv)
{
    extern __shared__ __align__(16) char dsm[];

    const int p = blockIdx.y;
    // NOTE: reference swaps inputs (query proj applied to k, key proj to q).
    const float* X    = (p == 0) ? k  : (p == 1) ? q  : v;
    const float* bias = (p == 0) ? bq : (p == 1) ? bk : bv;
    const bf16* Wh = g_wh + (size_t)p * DH_ * DM_;
    const bf16* Wl = g_wl + (size_t)p * DH_ * DM_;

    const int row0 = blockIdx.x * 128;
    const int tid  = threadIdx.x;
    const int lane = tid & 31;
    const int w    = tid >> 5;
    const int g    = lane >> 2;
    const int c    = lane & 3;
    const int wr   = w * 16;

    // stage pointers
    auto stageX  = [&](int s) { return (float*)(dsm + s * PSTAGE_BYTES); };
    auto stageWh = [&](int s) { return (bf16*)(dsm + s * PSTAGE_BYTES + 128 * PXSTR * 4); };
    auto stageWl = [&](int s) { return (bf16*)(dsm + s * PSTAGE_BYTES + 128 * PXSTR * 4 + 64 * PWSTR * 2); };

    auto issue_tile = [&](int tile, int s) {
        const int kb = tile * PK;
        uint32_t aX  = sm_u32(stageX(s));
        uint32_t aWh = sm_u32(stageWh(s));
        uint32_t aWl = sm_u32(stageWl(s));
        const char* pX  = (const char*)(X + (size_t)row0 * DM_ + kb);
        const char* pWh = (const char*)(Wh + kb);
        const char* pWl = (const char*)(Wl + kb);
        // X: 128 rows x 128B = 1024 chunks
        for (int i = tid; i < 1024; i += 256) {
            int r = i >> 3, ch = (i & 7) * 16;
            cp16(aX + r * (PXSTR * 4) + ch, pX + (size_t)r * (DM_ * 4) + ch);
        }
        // W: 64 rows x 64B = 256 chunks each
        {
            int r = tid >> 2, ch = (tid & 3) * 16;
            cp16(aWh + r * (PWSTR * 2) + ch, pWh + (size_t)r * (DM_ * 2) + ch);
            cp16(aWl + r * (PWSTR * 2) + ch, pWl + (size_t)r * (DM_ * 2) + ch);
        }
    };

    float acc[8][4];
#pragma unroll
    for (int i = 0; i < 8; i++)
#pragma unroll
        for (int j = 0; j < 4; j++) acc[i][j] = 0.f;

    constexpr int NT = DM_ / PK;   // 64
    issue_tile(0, 0);
    CP_COMMIT();

    for (int t = 0; t < NT; t++) {
        if (t + 1 < NT) { issue_tile(t + 1, (t + 1) & 1); CP_COMMIT(); }
        if (t + 1 < NT) cp_wait<1>(); else cp_wait<0>();
        __syncthreads();

        const float* sX = stageX(t & 1);
        const bf16*  sH = stageWh(t & 1);
        const bf16*  sL = stageWl(t & 1);

#pragma unroll
        for (int kk = 0; kk < PK; kk += 16) {
            // A fragments: convert fp32 -> hi/lo at load time
            uint32_t ah[4], al[4];
            {
                const int r = wr + g;
                float2 f0 = *(const float2*)&sX[(r)     * PXSTR + kk + 2 * c];
                float2 f1 = *(const float2*)&sX[(r + 8) * PXSTR + kk + 2 * c];
                float2 f2 = *(const float2*)&sX[(r)     * PXSTR + kk + 2 * c + 8];
                float2 f3 = *(const float2*)&sX[(r + 8) * PXSTR + kk + 2 * c + 8];
                split2(f0.x, f0.y, ah[0], al[0]);
                split2(f1.x, f1.y, ah[1], al[1]);
                split2(f2.x, f2.y, ah[2], al[2]);
                split2(f3.x, f3.y, ah[3], al[3]);
            }
#pragma unroll
            for (int nb = 0; nb < 8; nb++) {
                const int bbase = (nb * 8 + g) * PWSTR + kk + 2 * c;
                uint32_t bh[2], bl[2];
                bh[0] = *reinterpret_cast<const uint32_t*>(&sH[bbase]);
                bh[1] = *reinterpret_cast<const uint32_t*>(&sH[bbase + 8]);
                bl[0] = *reinterpret_cast<const uint32_t*>(&sL[bbase]);
                bl[1] = *reinterpret_cast<const uint32_t*>(&sL[bbase + 8]);
                mma_bf16(acc[nb], ah, bh);   // hi*hi
                mma_bf16(acc[nb], ah, bl);   // hi*lo
                mma_bf16(acc[nb], al, bh);   // lo*hi
            }
        }
        __syncthreads();
    }

    // Epilogue
    const float fold = (p == 0) ? FOLD : 1.0f;
    bf16* outH = (p == 0) ? g_qh_hi : (p == 1) ? g_kh_hi : g_vt_hi;
    bf16* outL = (p == 0) ? g_qh_lo : (p == 1) ? g_kh_lo : g_vt_lo;

#pragma unroll
    for (int nb = 0; nb < 8; nb++) {
        const int col = nb * 8 + 2 * c;
        const float b0f = bias[col];
        const float b1f = bias[col + 1];
        const int r0 = row0 + wr + g;
        float v00 = (acc[nb][0] + b0f) * fold;
        float v01 = (acc[nb][1] + b1f) * fold;
        float v10 = (acc[nb][2] + b0f) * fold;
        float v11 = (acc[nb][3] + b1f) * fold;
        if (p < 2) {
            uint32_t hp, lp;
            split2(v00, v01, hp, lp);
            *reinterpret_cast<uint32_t*>(&outH[(size_t)r0 * 64 + col]) = hp;
            *reinterpret_cast<uint32_t*>(&outL[(size_t)r0 * 64 + col]) = lp;
            split2(v10, v11, hp, lp);
            *reinterpret_cast<uint32_t*>(&outH[(size_t)(r0 + 8) * 64 + col]) = hp;
            *reinterpret_cast<uint32_t*>(&outL[(size_t)(r0 + 8) * 64 + col]) = lp;
        } else {
            // transposed store: [b][d][s]
            const int bidx = r0 >> 12;
            const int s0   = r0 & 4095;
            const size_t base = (size_t)bidx * 64;
            float vals[4]   = {v00, v01, v10, v11};
            int   dcol[4]   = {col, col + 1, col, col + 1};
            int   srow[4]   = {s0, s0, s0 + 8, s0 + 8};
#pragma unroll
            for (int j = 0; j < 4; j++) {
                bf16 h = __float2bfloat16(vals[j]);
                outH[(base + dcol[j]) * S_ + srow[j]] = h;
                outL[(base + dcol[j]) * S_ + srow[j]] =
                    __float2bfloat16(vals[j] - __bfloat162float(h));
            }
        }
    }
}

// ---------------------------------------------------------------------------
// Flash-attention kernel. grid = (S/64, B, SPLIT). 128 threads = 4 warps.
// Each block processes S/SPLIT keys, writes partial (o, m, l).
// Double-buffered K/V tiles via cp.async.
// ---------------------------------------------------------------------------
constexpr int ASTR = 72;                       // bf16 elements per smem row
constexpr int ASTAGE = 4 * 64 * ASTR;          // elements per stage (4 arrays)

__global__ __launch_bounds__(128) void attn_kernel()
{
    extern __shared__ __align__(16) char dsm_c[];
    bf16* dsm = (bf16*)dsm_c;

    const int qx   = blockIdx.x;
    const int b    = blockIdx.y;
    const int sp   = blockIdx.z;
    const int tid  = threadIdx.x;
    const int lane = tid & 31;
    const int w    = tid >> 5;
    const int g    = lane >> 2;
    const int c    = lane & 3;
    const int wr   = w * 16;
    const int row0 = b * S_ + qx * 64;

    constexpr int NT  = S_ / 64 / SPLIT;       // 16 key tiles per block
    const int jt0 = sp * NT;

    // Q fragments (hi/lo), register resident
    uint32_t qh[4][4], ql[4][4];
    {
        const bf16* baseH = g_qh_hi + (size_t)row0 * 64;
        const bf16* baseL = g_qh_lo + (size_t)row0 * 64;
        const int r = wr + g;
#pragma unroll
        for (int kk4 = 0; kk4 < 4; kk4++) {
            const int col = kk4 * 16 + 2 * c;
            qh[kk4][0] = *reinterpret_cast<const uint32_t*>(&baseH[(size_t)r * 64 + col]);
            qh[kk4][1] = *reinterpret_cast<const uint32_t*>(&baseH[(size_t)(r + 8) * 64 + col]);
            qh[kk4][2] = *reinterpret_cast<const uint32_t*>(&baseH[(size_t)r * 64 + col + 8]);
            qh[kk4][3] = *reinterpret_cast<const uint32_t*>(&baseH[(size_t)(r + 8) * 64 + col + 8]);
            ql[kk4][0] = *reinterpret_cast<const uint32_t*>(&baseL[(size_t)r * 64 + col]);
            ql[kk4][1] = *reinterpret_cast<const uint32_t*>(&baseL[(size_t)(r + 8) * 64 + col]);
            ql[kk4][2] = *reinterpret_cast<const uint32_t*>(&baseL[(size_t)r * 64 + col + 8]);
            ql[kk4][3] = *reinterpret_cast<const uint32_t*>(&baseL[(size_t)(r + 8) * 64 + col + 8]);
        }
    }

    auto issue_tile = [&](int jt, int s) {
        bf16* base = dsm + s * ASTAGE;
        uint32_t aKh = sm_u32(base);
        uint32_t aKl = aKh + 64 * ASTR * 2;
        uint32_t aVh = aKl + 64 * ASTR * 2;
        uint32_t aVl = aVh + 64 * ASTR * 2;
        const size_t kOff = (size_t)(b * S_ + jt * 64) * 64 * 2;   // bytes
        const char* pKh = (const char*)g_kh_hi + kOff;
        const char* pKl = (const char*)g_kh_lo + kOff;
        const char* pVh = (const char*)g_vt_hi + (size_t)b * 64 * S_ * 2 + (size_t)jt * 128;
        const char* pVl = (const char*)g_vt_lo + (size_t)b * 64 * S_ * 2 + (size_t)jt * 128;
        for (int i = tid; i < 512; i += 128) {
            int r = i >> 3, ch = (i & 7) * 16;
            cp16(aKh + r * 144 + ch, pKh + (size_t)r * 128 + ch);
            cp16(aKl + r * 144 + ch, pKl + (size_t)r * 128 + ch);
            cp16(aVh + r * 144 + ch, pVh + (size_t)r * (S_ * 2) + ch);
            cp16(aVl + r * 144 + ch, pVl + (size_t)r * (S_ * 2) + ch);
        }
    };

    float o[8][4];
#pragma unroll
    for (int i = 0; i < 8; i++)
#pragma unroll
        for (int j = 0; j < 4; j++) o[i][j] = 0.f;
    float m0 = -1e30f, m1 = -1e30f, l0 = 0.f, l1 = 0.f;

    issue_tile(jt0, 0);
    CP_COMMIT();

    for (int t = 0; t < NT; t++) {
        if (t + 1 < NT) { issue_tile(jt0 + t + 1, (t + 1) & 1); CP_COMMIT(); }
        if (t + 1 < NT) cp_wait<1>(); else cp_wait<0>();
        __syncthreads();

        const bf16* sKh = dsm + (t & 1) * ASTAGE;
        const bf16* sKl = sKh + 64 * ASTR;
        const bf16* sVh = sKl + 64 * ASTR;
        const bf16* sVl = sVh + 64 * ASTR;

        // S = Q K^T (3xBF16)
        float s[8][4];
#pragma unroll
        for (int i = 0; i < 8; i++)
#pragma unroll
            for (int j = 0; j < 4; j++) s[i][j] = 0.f;
#pragma unroll
        for (int kk4 = 0; kk4 < 4; kk4++) {
#pragma unroll
            for (int nb = 0; nb < 8; nb++) {
                const int bbase = (nb * 8 + g) * ASTR + kk4 * 16 + 2 * c;
                uint32_t bh[2], bl[2];
                bh[0] = *reinterpret_cast<const uint32_t*>(&sKh[bbase]);
                bh[1] = *reinterpret_cast<const uint32_t*>(&sKh[bbase + 8]);
                bl[0] = *reinterpret_cast<const uint32_t*>(&sKl[bbase]);
                bl[1] = *reinterpret_cast<const uint32_t*>(&sKl[bbase + 8]);
                mma_bf16(s[nb], qh[kk4], bh);
                mma_bf16(s[nb], qh[kk4], bl);
                mma_bf16(s[nb], ql[kk4], bh);
            }
        }

        // Online softmax (exp2 domain)
        float tm0 = -1e30f, tm1 = -1e30f;
#pragma unroll
        for (int nb = 0; nb < 8; nb++) {
            tm0 = fmaxf(tm0, fmaxf(s[nb][0], s[nb][1]));
            tm1 = fmaxf(tm1, fmaxf(s[nb][2], s[nb][3]));
        }
        tm0 = fmaxf(tm0, __shfl_xor_sync(0xffffffffu, tm0, 1));
        tm0 = fmaxf(tm0, __shfl_xor_sync(0xffffffffu, tm0, 2));
        tm1 = fmaxf(tm1, __shfl_xor_sync(0xffffffffu, tm1, 1));
        tm1 = fmaxf(tm1, __shfl_xor_sync(0xffffffffu, tm1, 2));
        const float nm0 = fmaxf(m0, tm0);
        const float nm1 = fmaxf(m1, tm1);
        const float al0 = fast_exp2(m0 - nm0);
        const float al1 = fast_exp2(m1 - nm1);
        m0 = nm0; m1 = nm1;
        float rs0 = 0.f, rs1 = 0.f;
#pragma unroll
        for (int nb = 0; nb < 8; nb++) {
            s[nb][0] = fast_exp2(s[nb][0] - m0); rs0 += s[nb][0];
            s[nb][1] = fast_exp2(s[nb][1] - m0); rs0 += s[nb][1];
            s[nb][2] = fast_exp2(s[nb][2] - m1); rs1 += s[nb][2];
            s[nb][3] = fast_exp2(s[nb][3] - m1); rs1 += s[nb][3];
        }
        rs0 += __shfl_xor_sync(0xffffffffu, rs0, 1);
        rs0 += __shfl_xor_sync(0xffffffffu, rs0, 2);
        rs1 += __shfl_xor_sync(0xffffffffu, rs1, 1);
        rs1 += __shfl_xor_sync(0xffffffffu, rs1, 2);
        l0 = l0 * al0 + rs0;
        l1 = l1 * al1 + rs1;
#pragma unroll
        for (int nb = 0; nb < 8; nb++) {
            o[nb][0] *= al0; o[nb][1] *= al0;
            o[nb][2] *= al1; o[nb][3] *= al1;
        }

        // O += P V (3xBF16)
#pragma unroll
        for (int ku = 0; ku < 4; ku++) {
            uint32_t ph[4], pl[4];
            split2(s[2 * ku][0],     s[2 * ku][1],     ph[0], pl[0]);
            split2(s[2 * ku][2],     s[2 * ku][3],     ph[1], pl[1]);
            split2(s[2 * ku + 1][0], s[2 * ku + 1][1], ph[2], pl[2]);
            split2(s[2 * ku + 1][2], s[2 * ku + 1][3], ph[3], pl[3]);
#pragma unroll
            for (int nbd = 0; nbd < 8; nbd++) {
                const int vbase = (nbd * 8 + g) * ASTR + ku * 16 + 2 * c;
                uint32_t vh2[2], vl2[2];
                vh2[0] = *reinterpret_cast<const uint32_t*>(&sVh[vbase]);
                vh2[1] = *reinterpret_cast<const uint32_t*>(&sVh[vbase + 8]);
                vl2[0] = *reinterpret_cast<const uint32_t*>(&sVl[vbase]);
                vl2[1] = *reinterpret_cast<const uint32_t*>(&sVl[vbase + 8]);
                mma_bf16(o[nbd], ph, vh2);
                mma_bf16(o[nbd], ph, vl2);
                mma_bf16(o[nbd], pl, vh2);
            }
        }
        __syncthreads();
    }

    // Write partials (unnormalized o, plus m and l per row)
    {
        const int rA = row0 + wr + g;        // first row
        float* po = g_po + ((size_t)sp * MT_) * 64;
#pragma unroll
        for (int nbd = 0; nbd < 8; nbd++) {
            const int colD = nbd * 8 + 2 * c;
            *reinterpret_cast<float2*>(&po[(size_t)rA * 64 + colD]) =
                make_float2(o[nbd][0], o[nbd][1]);
            *reinterpret_cast<float2*>(&po[(size_t)(rA + 8) * 64 + colD]) =
                make_float2(o[nbd][2], o[nbd][3]);
        }
        if (c == 0) {
            g_pm[(size_t)sp * MT_ + rA]     = m0;
            g_pl[(size_t)sp * MT_ + rA]     = l0;
            g_pm[(size_t)sp * MT_ + rA + 8] = m1;
            g_pl[(size_t)sp * MT_ + rA + 8] = l1;
        }
    }
}

// ---------------------------------------------------------------------------
// Combine split partials -> final output
// ---------------------------------------------------------------------------
__global__ void combine_kernel(float* __restrict__ out) {
    int idx = blockIdx.x * 256 + threadIdx.x;
    if (idx >= MT_ * 64) return;
    int r = idx >> 6;
    float mv[SPLIT];
    float M = -1e30f;
#pragma unroll
    for (int s = 0; s < SPLIT; s++) {
        mv[s] = g_pm[(size_t)s * MT_ + r];
        M = fmaxf(M, mv[s]);
    }
    float num = 0.f, den = 0.f;
#pragma unroll
    for (int s = 0; s < SPLIT; s++) {
        float wgt = fast_exp2(mv[s] - M);
        num += wgt * g_po[((size_t)s * MT_ + r) * 64 + (idx & 63)];
        den += wgt * g_pl[(size_t)s * MT_ + r];
    }
    out[idx] = num / den;
}

// ---------------------------------------------------------------------------
// kernel_launch
// ---------------------------------------------------------------------------
extern "C" void kernel_launch(void* const* d_in, const int* in_sizes, int n_in,
                              void* d_out, int out_size) {
    (void)in_sizes; (void)n_in; (void)out_size;
    const float* q  = (const float*)d_in[0];
    const float* k  = (const float*)d_in[1];
    const float* v  = (const float*)d_in[2];
    const float* Wq = (const float*)d_in[3];
    const float* bq = (const float*)d_in[4];
    const float* Wk = (const float*)d_in[5];
    const float* bk = (const float*)d_in[6];
    const float* Wv = (const float*)d_in[7];
    const float* bv = (const float*)d_in[8];
    float* out = (float*)d_out;

    constexpr int PROJ_SMEM = 2 * PSTAGE_BYTES;            // 57344
    constexpr int ATTN_SMEM = 2 * ASTAGE * (int)sizeof(bf16);  // 73728
    cudaFuncSetAttribute(proj_kernel, cudaFuncAttributeMaxDynamicSharedMemorySize, PROJ_SMEM);
    cudaFuncSetAttribute(attn_kernel, cudaFuncAttributeMaxDynamicSharedMemorySize, ATTN_SMEM);

    wsplit_kernel<<<(3 * DH_ * DM_ + 255) / 256, 256>>>(Wq, Wk, Wv);
    proj_kernel<<<dim3(MT_ / 128, 3), 256, PROJ_SMEM>>>(q, k, v, bq, bk, bv);
    attn_kernel<<<dim3(S_ / 64, B_, SPLIT), 128, ATTN_SMEM>>>();
    combine_kernel<<<(MT_ * 64 + 255) / 256, 256>>>(out);
}